// round 3
// baseline (speedup 1.0000x reference)
#include <cuda_runtime.h>

#define N_NODES 200000
#define N_EDGES 6400000
#define D_IN    100
#define D_H1    65
#define H1P     68      // padded to 17 float4s
#define D_H2    64      // 16 float4s

// ---------------- scratch (device globals; no allocation allowed) -----------
__device__ float4 g_h1  [(N_NODES * H1P) / 4];   // 54.4 MB
__device__ float4 g_agg1[(N_NODES * H1P) / 4];   // 54.4 MB
__device__ float4 g_h2  [(N_NODES * D_H2) / 4];  // 51.2 MB
__device__ float4 g_agg2[(N_NODES * D_H2) / 4];  // 51.2 MB
__device__ float  g_dinv[N_NODES];
__device__ int    g_deg [N_NODES];
__device__ float  g_norm[N_EDGES];

// ---------------- degree / norm --------------------------------------------
__global__ void k_deg_init() {
    int i = blockIdx.x * blockDim.x + threadIdx.x;
    if (i < N_NODES) g_deg[i] = 1;               // self loop contributes 1
}

__global__ void k_deg_count(const int* __restrict__ ei) {
    int e = blockIdx.x * blockDim.x + threadIdx.x;
    if (e < N_EDGES) atomicAdd(&g_deg[ei[N_EDGES + e]], 1);   // col = ei[1]
}

__global__ void k_dinv() {
    int i = blockIdx.x * blockDim.x + threadIdx.x;
    if (i < N_NODES) g_dinv[i] = rsqrtf((float)g_deg[i]);
}

__global__ void k_norm(const int* __restrict__ ei) {
    int e = blockIdx.x * blockDim.x + threadIdx.x;
    if (e < N_EDGES)
        g_norm[e] = g_dinv[ei[e]] * g_dinv[ei[N_EDGES + e]];
}

// ---------------- GEMM1: h1 = x @ W1 ; agg1 = h1 * dinv^2 (self loop) -------
__global__ __launch_bounds__(256) void k_gemm1(const float* __restrict__ x,
                                               const float* __restrict__ W1) {
    __shared__ float Ws[D_IN * H1P];   // 100x68, padded cols zeroed (27.2 KB)
    __shared__ float xs[128 * 25];     // 12.8 KB
    int t = threadIdx.x;

    for (int idx = t; idx < D_IN * H1P; idx += 256) {
        int k = idx / H1P, c = idx % H1P;
        Ws[idx] = (c < D_H1) ? W1[k * D_H1 + c] : 0.0f;
    }

    int g     = t & 3;
    int rp    = (t >> 2) * 2;
    int rbase = blockIdx.x * 128;

    float acc0[17], acc1[17];
#pragma unroll
    for (int j = 0; j < 17; j++) { acc0[j] = 0.0f; acc1[j] = 0.0f; }

    for (int kc = 0; kc < 4; kc++) {               // k chunks of 25
        __syncthreads();
        for (int idx = t; idx < 128 * 25; idx += 256) {
            int rr = idx / 25, kk = idx % 25;
            int r = rbase + rr;
            xs[idx] = (r < N_NODES) ? x[r * D_IN + kc * 25 + kk] : 0.0f;
        }
        __syncthreads();
        for (int kk = 0; kk < 25; kk++) {
            float xv0 = xs[rp * 25 + kk];
            float xv1 = xs[rp * 25 + 25 + kk];
            const float* wr = &Ws[(kc * 25 + kk) * H1P + g];
#pragma unroll
            for (int j = 0; j < 17; j++) {
                float w = wr[4 * j];
                acc0[j] += xv0 * w;
                acc1[j] += xv1 * w;
            }
        }
    }

    float* h1f = (float*)g_h1;
    float* a1f = (float*)g_agg1;
    int r0 = rbase + rp;
    if (r0 < N_NODES) {
        float d = g_dinv[r0], d2 = d * d;
#pragma unroll
        for (int j = 0; j < 17; j++) {
            int c = g + 4 * j;
            float v = acc0[j];
            h1f[r0 * H1P + c] = v;
            a1f[r0 * H1P + c] = v * d2;
        }
    }
    int r1 = r0 + 1;
    if (r1 < N_NODES) {
        float d = g_dinv[r1], d2 = d * d;
#pragma unroll
        for (int j = 0; j < 17; j++) {
            int c = g + 4 * j;
            float v = acc1[j];
            h1f[r1 * H1P + c] = v;
            a1f[r1 * H1P + c] = v * d2;
        }
    }
}

// ---------------- GEMM2: h2 = relu(agg1 + b1) @ W2 ; agg2 = h2 * dinv^2 -----
__global__ __launch_bounds__(256) void k_gemm2(const float* __restrict__ W2,
                                               const float* __restrict__ b1) {
    __shared__ float Ws[D_H1 * D_H2];  // 65x64 (16.6 KB)
    __shared__ float xs[128 * 33];     // 16.9 KB (stride 33, conflict-free)
    const float* a1f = (const float*)g_agg1;
    int t = threadIdx.x;

    for (int idx = t; idx < D_H1 * D_H2; idx += 256) Ws[idx] = W2[idx];

    int g     = t & 3;
    int rp    = (t >> 2) * 2;
    int rbase = blockIdx.x * 128;

    float acc0[16], acc1[16];
#pragma unroll
    for (int j = 0; j < 16; j++) { acc0[j] = 0.0f; acc1[j] = 0.0f; }

    int k0 = 0;
    for (int kc = 0; kc < 2; kc++) {               // chunks of 33 + 32
        int len = kc ? 32 : 33;
        __syncthreads();
        for (int idx = t; idx < 128 * len; idx += 256) {
            int rr = idx / len, kk = idx % len;
            int r = rbase + rr, k = k0 + kk;
            xs[rr * 33 + kk] =
                (r < N_NODES) ? fmaxf(a1f[r * H1P + k] + b1[k], 0.0f) : 0.0f;
        }
        __syncthreads();
        for (int kk = 0; kk < len; kk++) {
            float xv0 = xs[rp * 33 + kk];
            float xv1 = xs[(rp + 1) * 33 + kk];
            const float* wr = &Ws[(k0 + kk) * D_H2 + g];
#pragma unroll
            for (int j = 0; j < 16; j++) {
                float w = wr[4 * j];
                acc0[j] += xv0 * w;
                acc1[j] += xv1 * w;
            }
        }
        k0 += len;
    }

    float* h2f = (float*)g_h2;
    float* a2f = (float*)g_agg2;
    int r0 = rbase + rp;
    if (r0 < N_NODES) {
        float d = g_dinv[r0], d2 = d * d;
#pragma unroll
        for (int j = 0; j < 16; j++) {
            int c = g + 4 * j;
            float v = acc0[j];
            h2f[r0 * D_H2 + c] = v;
            a2f[r0 * D_H2 + c] = v * d2;
        }
    }
    int r1 = r0 + 1;
    if (r1 < N_NODES) {
        float d = g_dinv[r1], d2 = d * d;
#pragma unroll
        for (int j = 0; j < 16; j++) {
            int c = g + 4 * j;
            float v = acc1[j];
            h2f[r1 * D_H2 + c] = v;
            a2f[r1 * D_H2 + c] = v * d2;
        }
    }
}

// ---------------- edge aggregation: dst[col] += src[row] * norm -------------
// EPB edges per block, D4 float4-chunks per edge; blockDim = EPB*D4.
template <int D4, int EPB, bool LAYER1>
__global__ __launch_bounds__(D4 * EPB) void k_agg(const int* __restrict__ ei) {
    int      t  = threadIdx.x;
    int      le = t / D4;                 // compile-time constant divisor
    int      c  = t - le * D4;
    unsigned e  = blockIdx.x * EPB + le;
    if (e >= N_EDGES) return;

    int   r  = __ldg(&ei[e]);
    int   cl = __ldg(&ei[N_EDGES + e]);
    float nr = __ldg(&g_norm[e]);

    const float4* src = LAYER1 ? (const float4*)g_h1 : (const float4*)g_h2;
    float4*       dst = LAYER1 ? g_agg1 : g_agg2;

    float4 v = __ldg(&src[(unsigned)r * D4 + c]);
    v.x *= nr; v.y *= nr; v.z *= nr; v.w *= nr;

    float4* p = &dst[(unsigned)cl * D4 + c];
#if __CUDA_ARCH__ >= 900
    asm volatile("red.global.add.v4.f32 [%0], {%1, %2, %3, %4};"
                 :: "l"(p), "f"(v.x), "f"(v.y), "f"(v.z), "f"(v.w)
                 : "memory");
#else
    float* pf = (float*)p;
    atomicAdd(pf + 0, v.x);
    atomicAdd(pf + 1, v.y);
    atomicAdd(pf + 2, v.z);
    atomicAdd(pf + 3, v.w);
#endif
}

// ---------------- output: relu( relu(agg2 + b2) @ Wout + bout ) -------------
__global__ __launch_bounds__(256) void k_out(const float* __restrict__ b2,
                                             const float* __restrict__ Wout,
                                             const float* __restrict__ bout,
                                             float* __restrict__ out) {
    int gt   = blockIdx.x * blockDim.x + threadIdx.x;
    int i    = gt >> 5;
    int lane = gt & 31;
    if (i >= N_NODES) return;
    const float* a2f = (const float*)g_agg2;

    float s = fmaxf(a2f[i * D_H2 + lane]      + b2[lane],      0.0f) * Wout[lane]
            + fmaxf(a2f[i * D_H2 + lane + 32] + b2[lane + 32], 0.0f) * Wout[lane + 32];
#pragma unroll
    for (int o = 16; o > 0; o >>= 1) s += __shfl_xor_sync(0xffffffffu, s, o);
    if (lane == 0) out[i] = fmaxf(s + bout[0], 0.0f);
}

// ---------------- launch ----------------------------------------------------
extern "C" void kernel_launch(void* const* d_in, const int* in_sizes, int n_in,
                              void* d_out, int out_size) {
    const float* x    = (const float*)d_in[0];
    const int*   ei   = (const int*)  d_in[1];
    const float* W1   = (const float*)d_in[2];
    const float* b1   = (const float*)d_in[3];
    const float* W2   = (const float*)d_in[4];
    const float* b2   = (const float*)d_in[5];
    const float* Wout = (const float*)d_in[6];
    const float* bout = (const float*)d_in[7];
    float* out = (float*)d_out;

    const int NB_N  = (N_NODES + 255) / 256;
    const int NB_E  = (N_EDGES + 255) / 256;
    const int NB_G  = (N_NODES + 127) / 128;
    const int NB_A1 = (N_EDGES + 15) / 16;   // 16 edges/block, 272 threads
    const int NB_A2 = (N_EDGES + 15) / 16;   // 16 edges/block, 256 threads
    const int NB_O  = (N_NODES * 32 + 255) / 256;

    k_deg_init <<<NB_N, 256>>>();
    k_deg_count<<<NB_E, 256>>>(ei);
    k_dinv     <<<NB_N, 256>>>();
    k_norm     <<<NB_E, 256>>>(ei);
    k_gemm1    <<<NB_G, 256>>>(x, W1);
    k_agg<17, 16, true>  <<<NB_A1, 17 * 16>>>(ei);
    k_gemm2    <<<NB_G, 256>>>(W2, b1);
    k_agg<16, 16, false> <<<NB_A2, 16 * 16>>>(ei);
    k_out      <<<NB_O, 256>>>(b2, Wout, bout, out);
}

// round 4
// speedup vs baseline: 1.9762x; 1.9762x over previous
#include <cuda_runtime.h>
#include <cuda_fp16.h>

#define N_NODES 200000
#define N_EDGES 6400000
#define D_IN    100
#define D_H1    65
#define H1P     68      // fp32 compute pad (17 float4)
#define H1H     72      // fp16 row pad: 9 x uint4 (8 halves each) = 144B
#define D_H2    64      // fp16 row: 8 x uint4 = 128B

// ---------------- scratch (device globals; no allocation allowed) -----------
__device__ uint4  g_h1h [(N_NODES * H1H) / 8];   // 28.8 MB  fp16 h1*dinv (L2-resident)
__device__ uint4  g_h2h [(N_NODES * D_H2) / 8];  // 25.6 MB  fp16 h2*dinv (L2-resident)
__device__ float4 g_agg1[(N_NODES * H1H) / 4];   // 57.6 MB  fp32 layer-1 aggregate
__device__ float  g_dinv[N_NODES];
__device__ int    g_deg [N_NODES];
__device__ int    g_rowptr[N_NODES + 1];
__device__ int    g_cursor[N_NODES];
__device__ int    g_esrc[N_EDGES];               // CSR: src ids grouped by dst

// ---------------- degree / dinv ---------------------------------------------
__global__ void k_deg_zero() {
    int i = blockIdx.x * blockDim.x + threadIdx.x;
    if (i < N_NODES) g_deg[i] = 0;
}

__global__ void k_deg_count(const int* __restrict__ ei) {
    int e = blockIdx.x * blockDim.x + threadIdx.x;
    if (e < N_EDGES) atomicAdd(&g_deg[ei[N_EDGES + e]], 1);   // dst = ei[1]
}

__global__ void k_dinv() {
    int i = blockIdx.x * blockDim.x + threadIdx.x;
    if (i < N_NODES) g_dinv[i] = rsqrtf((float)(g_deg[i] + 1));  // +1 self loop
}

// ---------------- exclusive scan of deg -> rowptr (single block) ------------
__global__ void k_scan() {
    __shared__ int wsum[32];
    __shared__ int carry_s;
    int t = threadIdx.x, lane = t & 31, wid = t >> 5;
    if (t == 0) carry_s = 0;
    __syncthreads();
    for (int base = 0; base < N_NODES; base += 1024) {
        int idx = base + t;
        int v = (idx < N_NODES) ? g_deg[idx] : 0;
        int x = v;
#pragma unroll
        for (int off = 1; off < 32; off <<= 1) {
            int n = __shfl_up_sync(0xffffffffu, x, off);
            if (lane >= off) x += n;
        }
        if (lane == 31) wsum[wid] = x;
        __syncthreads();
        if (wid == 0) {
            int w = wsum[lane];
#pragma unroll
            for (int off = 1; off < 32; off <<= 1) {
                int n = __shfl_up_sync(0xffffffffu, w, off);
                if (lane >= off) w += n;
            }
            wsum[lane] = w;   // inclusive warp totals
        }
        __syncthreads();
        int warpoff = (wid > 0) ? wsum[wid - 1] : 0;
        int excl = x - v + warpoff + carry_s;
        if (idx < N_NODES) { g_rowptr[idx] = excl; g_cursor[idx] = excl; }
        int total = wsum[31];
        __syncthreads();
        if (t == 0) carry_s += total;
        __syncthreads();
    }
    if (t == 0) g_rowptr[N_NODES] = carry_s;
}

// ---------------- scatter edges into CSR ------------------------------------
__global__ void k_scatter(const int* __restrict__ ei) {
    int e = blockIdx.x * blockDim.x + threadIdx.x;
    if (e < N_EDGES) {
        int s = ei[e];
        int d = ei[N_EDGES + e];
        int pos = atomicAdd(&g_cursor[d], 1);
        g_esrc[pos] = s;
    }
}

// ---------------- GEMM1: hs1 = (x @ W1) * dinv  -> fp16 ----------------------
__global__ __launch_bounds__(256) void k_gemm1(const float* __restrict__ x,
                                               const float* __restrict__ W1) {
    __shared__ float Ws[D_IN * H1P];   // 100x68, pad cols zero (27.2 KB)
    __shared__ float xs[128 * 25];     // 12.8 KB
    int t = threadIdx.x;

    for (int idx = t; idx < D_IN * H1P; idx += 256) {
        int k = idx / H1P, c = idx % H1P;
        Ws[idx] = (c < D_H1) ? W1[k * D_H1 + c] : 0.0f;
    }

    int g     = t & 3;
    int rp    = (t >> 2) * 2;
    int rbase = blockIdx.x * 128;

    float acc0[17], acc1[17];
#pragma unroll
    for (int j = 0; j < 17; j++) { acc0[j] = 0.0f; acc1[j] = 0.0f; }

    for (int kc = 0; kc < 4; kc++) {
        __syncthreads();
        for (int idx = t; idx < 128 * 25; idx += 256) {
            int rr = idx / 25, kk = idx % 25;
            int r = rbase + rr;
            xs[idx] = (r < N_NODES) ? x[r * D_IN + kc * 25 + kk] : 0.0f;
        }
        __syncthreads();
        for (int kk = 0; kk < 25; kk++) {
            float xv0 = xs[rp * 25 + kk];
            float xv1 = xs[rp * 25 + 25 + kk];
            const float* wr = &Ws[(kc * 25 + kk) * H1P + g];
#pragma unroll
            for (int j = 0; j < 17; j++) {
                float w = wr[4 * j];
                acc0[j] += xv0 * w;
                acc1[j] += xv1 * w;
            }
        }
    }

    __half* hs = (__half*)g_h1h;
    int r0 = rbase + rp;
    if (r0 < N_NODES) {
        float d = g_dinv[r0];
#pragma unroll
        for (int j = 0; j < 17; j++)
            hs[r0 * H1H + g + 4 * j] = __float2half_rn(acc0[j] * d);
        hs[r0 * H1H + 68 + g] = __float2half_rn(0.0f);   // zero pad 68..71
    }
    int r1 = r0 + 1;
    if (r1 < N_NODES) {
        float d = g_dinv[r1];
#pragma unroll
        for (int j = 0; j < 17; j++)
            hs[r1 * H1H + g + 4 * j] = __float2half_rn(acc1[j] * d);
        hs[r1 * H1H + 68 + g] = __float2half_rn(0.0f);
    }
}

// ---------------- fp16 chunk accumulate --------------------------------------
__device__ __forceinline__ void acc_chunk(float* a, uint4 q) {
    const __half2* hp = (const __half2*)&q;
#pragma unroll
    for (int j = 0; j < 4; j++) {
        float2 f = __half22float2(hp[j]);
        a[2 * j]     += f.x;
        a[2 * j + 1] += f.y;
    }
}

// ---------------- agg1: agg1[i] = dinv[i] * (hs1[i] + sum hs1[src]) ---------
// 9 chunk-threads per node, 32 nodes per 288-thread block.
__global__ __launch_bounds__(288) void k_agg1() {
    int t  = threadIdx.x;
    int ln = t / 9;
    int c  = t - ln * 9;
    int i  = blockIdx.x * 32 + ln;
    if (i >= N_NODES) return;

    const uint4* hs = (const uint4*)g_h1h;      // N x 9 chunks
    int beg = __ldg(&g_rowptr[i]);
    int end = __ldg(&g_rowptr[i + 1]);

    float a[8] = {0, 0, 0, 0, 0, 0, 0, 0};
    acc_chunk(a, __ldg(&hs[(unsigned)i * 9 + c]));      // self loop

    int k = beg;
    for (; k + 3 < end; k += 4) {
        int s0 = __ldg(&g_esrc[k]);
        int s1 = __ldg(&g_esrc[k + 1]);
        int s2 = __ldg(&g_esrc[k + 2]);
        int s3 = __ldg(&g_esrc[k + 3]);
        uint4 q0 = __ldg(&hs[(unsigned)s0 * 9 + c]);
        uint4 q1 = __ldg(&hs[(unsigned)s1 * 9 + c]);
        uint4 q2 = __ldg(&hs[(unsigned)s2 * 9 + c]);
        uint4 q3 = __ldg(&hs[(unsigned)s3 * 9 + c]);
        acc_chunk(a, q0); acc_chunk(a, q1); acc_chunk(a, q2); acc_chunk(a, q3);
    }
    for (; k < end; k++) {
        int s = __ldg(&g_esrc[k]);
        acc_chunk(a, __ldg(&hs[(unsigned)s * 9 + c]));
    }

    float d = __ldg(&g_dinv[i]);
    float4 o0 = make_float4(d * a[0], d * a[1], d * a[2], d * a[3]);
    float4 o1 = make_float4(d * a[4], d * a[5], d * a[6], d * a[7]);
    g_agg1[(unsigned)i * 18 + c * 2]     = o0;
    g_agg1[(unsigned)i * 18 + c * 2 + 1] = o1;
}

// ---------------- GEMM2: hs2 = (relu(agg1 + b1) @ W2) * dinv -> fp16 --------
__global__ __launch_bounds__(256) void k_gemm2(const float* __restrict__ W2,
                                               const float* __restrict__ b1) {
    __shared__ float Ws[D_H1 * D_H2];  // 65x64 (16.6 KB)
    __shared__ float xs[128 * 33];     // stride 33
    const float* a1f = (const float*)g_agg1;
    int t = threadIdx.x;

    for (int idx = t; idx < D_H1 * D_H2; idx += 256) Ws[idx] = W2[idx];

    int g     = t & 3;
    int rp    = (t >> 2) * 2;
    int rbase = blockIdx.x * 128;

    float acc0[16], acc1[16];
#pragma unroll
    for (int j = 0; j < 16; j++) { acc0[j] = 0.0f; acc1[j] = 0.0f; }

    int k0 = 0;
    for (int kc = 0; kc < 2; kc++) {
        int len = kc ? 32 : 33;
        __syncthreads();
        for (int idx = t; idx < 128 * len; idx += 256) {
            int rr = idx / len, kk = idx % len;
            int r = rbase + rr, k = k0 + kk;
            xs[rr * 33 + kk] =
                (r < N_NODES) ? fmaxf(a1f[(unsigned)r * H1H + k] + b1[k], 0.0f) : 0.0f;
        }
        __syncthreads();
        for (int kk = 0; kk < len; kk++) {
            float xv0 = xs[rp * 33 + kk];
            float xv1 = xs[(rp + 1) * 33 + kk];
            const float* wr = &Ws[(k0 + kk) * D_H2 + g];
#pragma unroll
            for (int j = 0; j < 16; j++) {
                float w = wr[4 * j];
                acc0[j] += xv0 * w;
                acc1[j] += xv1 * w;
            }
        }
        k0 += len;
    }

    __half* hs = (__half*)g_h2h;
    int r0 = rbase + rp;
    if (r0 < N_NODES) {
        float d = g_dinv[r0];
#pragma unroll
        for (int j = 0; j < 16; j++)
            hs[r0 * D_H2 + g + 4 * j] = __float2half_rn(acc0[j] * d);
    }
    int r1 = r0 + 1;
    if (r1 < N_NODES) {
        float d = g_dinv[r1];
#pragma unroll
        for (int j = 0; j < 16; j++)
            hs[r1 * D_H2 + g + 4 * j] = __float2half_rn(acc1[j] * d);
    }
}

// ------- agg2 + output fused: out[i]=relu(sum_c relu(agg2_c+b2)*Wout + bout) -
// 8 chunk-threads per node, 32 nodes per 256-thread block.
__global__ __launch_bounds__(256) void k_agg2out(const float* __restrict__ b2,
                                                 const float* __restrict__ Wout,
                                                 const float* __restrict__ bout,
                                                 float* __restrict__ out) {
    int t  = threadIdx.x;
    int ln = t >> 3;
    int c  = t & 7;
    int i  = blockIdx.x * 32 + ln;
    if (i >= N_NODES) return;

    const uint4* hs = (const uint4*)g_h2h;      // N x 8 chunks
    int beg = __ldg(&g_rowptr[i]);
    int end = __ldg(&g_rowptr[i + 1]);

    float a[8] = {0, 0, 0, 0, 0, 0, 0, 0};
    acc_chunk(a, __ldg(&hs[(unsigned)i * 8 + c]));      // self loop

    int k = beg;
    for (; k + 3 < end; k += 4) {
        int s0 = __ldg(&g_esrc[k]);
        int s1 = __ldg(&g_esrc[k + 1]);
        int s2 = __ldg(&g_esrc[k + 2]);
        int s3 = __ldg(&g_esrc[k + 3]);
        uint4 q0 = __ldg(&hs[(unsigned)s0 * 8 + c]);
        uint4 q1 = __ldg(&hs[(unsigned)s1 * 8 + c]);
        uint4 q2 = __ldg(&hs[(unsigned)s2 * 8 + c]);
        uint4 q3 = __ldg(&hs[(unsigned)s3 * 8 + c]);
        acc_chunk(a, q0); acc_chunk(a, q1); acc_chunk(a, q2); acc_chunk(a, q3);
    }
    for (; k < end; k++) {
        int s = __ldg(&g_esrc[k]);
        acc_chunk(a, __ldg(&hs[(unsigned)s * 8 + c]));
    }

    float d = __ldg(&g_dinv[i]);
    float4 b2a = __ldg((const float4*)b2 + c * 2);
    float4 b2b = __ldg((const float4*)b2 + c * 2 + 1);
    float4 woa = __ldg((const float4*)Wout + c * 2);
    float4 wob = __ldg((const float4*)Wout + c * 2 + 1);

    float s = fmaxf(d * a[0] + b2a.x, 0.0f) * woa.x
            + fmaxf(d * a[1] + b2a.y, 0.0f) * woa.y
            + fmaxf(d * a[2] + b2a.z, 0.0f) * woa.z
            + fmaxf(d * a[3] + b2a.w, 0.0f) * woa.w
            + fmaxf(d * a[4] + b2b.x, 0.0f) * wob.x
            + fmaxf(d * a[5] + b2b.y, 0.0f) * wob.y
            + fmaxf(d * a[6] + b2b.z, 0.0f) * wob.z
            + fmaxf(d * a[7] + b2b.w, 0.0f) * wob.w;

    s += __shfl_xor_sync(0xffffffffu, s, 1);
    s += __shfl_xor_sync(0xffffffffu, s, 2);
    s += __shfl_xor_sync(0xffffffffu, s, 4);
    if (c == 0) out[i] = fmaxf(s + __ldg(bout), 0.0f);
}

// ---------------- launch ----------------------------------------------------
extern "C" void kernel_launch(void* const* d_in, const int* in_sizes, int n_in,
                              void* d_out, int out_size) {
    const float* x    = (const float*)d_in[0];
    const int*   ei   = (const int*)  d_in[1];
    const float* W1   = (const float*)d_in[2];
    const float* b1   = (const float*)d_in[3];
    const float* W2   = (const float*)d_in[4];
    const float* b2   = (const float*)d_in[5];
    const float* Wout = (const float*)d_in[6];
    const float* bout = (const float*)d_in[7];
    float* out = (float*)d_out;

    const int NB_N = (N_NODES + 255) / 256;
    const int NB_E = (N_EDGES + 255) / 256;
    const int NB_G = (N_NODES + 127) / 128;
    const int NB_A = (N_NODES + 31) / 32;    // 6250

    k_deg_zero <<<NB_N, 256>>>();
    k_deg_count<<<NB_E, 256>>>(ei);
    k_dinv     <<<NB_N, 256>>>();
    k_scan     <<<1, 1024>>>();
    k_scatter  <<<NB_E, 256>>>(ei);
    k_gemm1    <<<NB_G, 256>>>(x, W1);
    k_agg1     <<<NB_A, 288>>>();
    k_gemm2    <<<NB_G, 256>>>(W2, b1);
    k_agg2out  <<<NB_A, 256>>>(b2, Wout, bout, out);
}

// round 5
// speedup vs baseline: 2.4545x; 1.2420x over previous
#include <cuda_runtime.h>
#include <cuda_fp16.h>

#define N_NODES 200000
#define N_EDGES 6400000
#define D_IN    100
#define D_H1    65
#define H1P     68      // fp32 compute pad (17 float4)
#define H1H     72      // fp16 row pad: 9 x uint4 (8 halves each) = 144B
#define D_H2    64      // fp16 row: 8 x uint4 = 128B

#define SCAN_B  1024
#define SCAN_NB ((N_NODES + SCAN_B - 1) / SCAN_B)   // 196

// ---------------- scratch (device globals; no allocation allowed) -----------
__device__ uint4  g_h1h [(N_NODES * H1H) / 8];   // 28.8 MB  fp16 h1*dinv (L2-resident)
__device__ uint4  g_h2h [(N_NODES * D_H2) / 8];  // 25.6 MB  fp16 h2*dinv (L2-resident)
__device__ float4 g_agg1[(N_NODES * H1H) / 4];   // 57.6 MB  fp32 layer-1 aggregate
__device__ float  g_dinv[N_NODES];
__device__ int    g_deg [N_NODES];
__device__ int    g_rowptr[N_NODES + 1];
__device__ int    g_cursor[N_NODES];
__device__ int    g_esrc[N_EDGES];               // CSR: src ids grouped by dst
__device__ int    g_bsum[SCAN_NB];               // per-block scan totals

// ---------------- degree / dinv ---------------------------------------------
__global__ void k_deg_zero() {
    int i = blockIdx.x * blockDim.x + threadIdx.x;
    if (i < N_NODES) g_deg[i] = 0;
}

__global__ void k_deg_count(const int* __restrict__ ei) {
    int e = blockIdx.x * blockDim.x + threadIdx.x;
    if (e < N_EDGES) atomicAdd(&g_deg[ei[N_EDGES + e]], 1);   // dst = ei[1]
}

__global__ void k_dinv() {
    int i = blockIdx.x * blockDim.x + threadIdx.x;
    if (i < N_NODES) g_dinv[i] = rsqrtf((float)(g_deg[i] + 1));  // +1 self loop
}

// ---------------- scan pass 1: per-block exclusive scan ----------------------
__global__ __launch_bounds__(SCAN_B) void k_scan1() {
    __shared__ int wsum[32];
    int t = threadIdx.x, lane = t & 31, wid = t >> 5;
    int idx = blockIdx.x * SCAN_B + t;
    int v = (idx < N_NODES) ? g_deg[idx] : 0;
    int x = v;
#pragma unroll
    for (int off = 1; off < 32; off <<= 1) {
        int n = __shfl_up_sync(0xffffffffu, x, off);
        if (lane >= off) x += n;
    }
    if (lane == 31) wsum[wid] = x;
    __syncthreads();
    if (wid == 0) {
        int w = wsum[lane];
#pragma unroll
        for (int off = 1; off < 32; off <<= 1) {
            int n = __shfl_up_sync(0xffffffffu, w, off);
            if (lane >= off) w += n;
        }
        wsum[lane] = w;   // inclusive warp totals
    }
    __syncthreads();
    int warpoff = (wid > 0) ? wsum[wid - 1] : 0;
    int excl = x - v + warpoff;                    // block-local exclusive
    if (idx < N_NODES) g_rowptr[idx] = excl;
    if (t == SCAN_B - 1) g_bsum[blockIdx.x] = warpoff + x;   // block total
}

// ---------------- scan pass 2: scan the 196 block totals (1 tiny block) -----
__global__ __launch_bounds__(256) void k_scan2() {
    __shared__ int wsum[8];
    int t = threadIdx.x, lane = t & 31, wid = t >> 5;
    int v = (t < SCAN_NB) ? g_bsum[t] : 0;
    int x = v;
#pragma unroll
    for (int off = 1; off < 32; off <<= 1) {
        int n = __shfl_up_sync(0xffffffffu, x, off);
        if (lane >= off) x += n;
    }
    if (lane == 31) wsum[wid] = x;
    __syncthreads();
    if (wid == 0 && lane < 8) {
        int w = wsum[lane];
#pragma unroll
        for (int off = 1; off < 8; off <<= 1) {
            int n = __shfl_up_sync(0xffu, w, off);
            if (lane >= off) w += n;
        }
        wsum[lane] = w;
    }
    __syncthreads();
    int warpoff = (wid > 0) ? wsum[wid - 1] : 0;
    int excl = x - v + warpoff;
    if (t < SCAN_NB) g_bsum[t] = excl;
    if (t == SCAN_NB - 1) g_rowptr[N_NODES] = excl + v;   // grand total
}

// ---------------- scan pass 3: add block offsets, init cursor ----------------
__global__ __launch_bounds__(SCAN_B) void k_scan3() {
    int idx = blockIdx.x * SCAN_B + threadIdx.x;
    if (idx < N_NODES) {
        int r = g_rowptr[idx] + g_bsum[blockIdx.x];
        g_rowptr[idx] = r;
        g_cursor[idx] = r;
    }
}

// ---------------- scatter edges into CSR ------------------------------------
__global__ void k_scatter(const int* __restrict__ ei) {
    int e = blockIdx.x * blockDim.x + threadIdx.x;
    if (e < N_EDGES) {
        int s = ei[e];
        int d = ei[N_EDGES + e];
        int pos = atomicAdd(&g_cursor[d], 1);
        g_esrc[pos] = s;
    }
}

// ---------------- GEMM1: hs1 = (x @ W1) * dinv  -> fp16 ----------------------
__global__ __launch_bounds__(256) void k_gemm1(const float* __restrict__ x,
                                               const float* __restrict__ W1) {
    __shared__ float Ws[D_IN * H1P];   // 100x68, pad cols zero (27.2 KB)
    __shared__ float xs[128 * 25];     // 12.8 KB
    int t = threadIdx.x;

    for (int idx = t; idx < D_IN * H1P; idx += 256) {
        int k = idx / H1P, c = idx % H1P;
        Ws[idx] = (c < D_H1) ? W1[k * D_H1 + c] : 0.0f;
    }

    int g     = t & 3;
    int rp    = (t >> 2) * 2;
    int rbase = blockIdx.x * 128;

    float acc0[17], acc1[17];
#pragma unroll
    for (int j = 0; j < 17; j++) { acc0[j] = 0.0f; acc1[j] = 0.0f; }

    for (int kc = 0; kc < 4; kc++) {
        __syncthreads();
        for (int idx = t; idx < 128 * 25; idx += 256) {
            int rr = idx / 25, kk = idx % 25;
            int r = rbase + rr;
            xs[idx] = (r < N_NODES) ? x[r * D_IN + kc * 25 + kk] : 0.0f;
        }
        __syncthreads();
        for (int kk = 0; kk < 25; kk++) {
            float xv0 = xs[rp * 25 + kk];
            float xv1 = xs[rp * 25 + 25 + kk];
            const float* wr = &Ws[(kc * 25 + kk) * H1P + g];
#pragma unroll
            for (int j = 0; j < 17; j++) {
                float w = wr[4 * j];
                acc0[j] += xv0 * w;
                acc1[j] += xv1 * w;
            }
        }
    }

    __half* hs = (__half*)g_h1h;
    int r0 = rbase + rp;
    if (r0 < N_NODES) {
        float d = g_dinv[r0];
#pragma unroll
        for (int j = 0; j < 17; j++)
            hs[r0 * H1H + g + 4 * j] = __float2half_rn(acc0[j] * d);
        hs[r0 * H1H + 68 + g] = __float2half_rn(0.0f);   // zero pad 68..71
    }
    int r1 = r0 + 1;
    if (r1 < N_NODES) {
        float d = g_dinv[r1];
#pragma unroll
        for (int j = 0; j < 17; j++)
            hs[r1 * H1H + g + 4 * j] = __float2half_rn(acc1[j] * d);
        hs[r1 * H1H + 68 + g] = __float2half_rn(0.0f);
    }
}

// ---------------- fp16 chunk accumulate --------------------------------------
__device__ __forceinline__ void acc_chunk(float* a, uint4 q) {
    const __half2* hp = (const __half2*)&q;
#pragma unroll
    for (int j = 0; j < 4; j++) {
        float2 f = __half22float2(hp[j]);
        a[2 * j]     += f.x;
        a[2 * j + 1] += f.y;
    }
}

// ---------------- agg1: agg1[i] = dinv[i] * (hs1[i] + sum hs1[src]) ---------
// 9 chunk-threads per node, 32 nodes per 288-thread block.
__global__ __launch_bounds__(288) void k_agg1() {
    int t  = threadIdx.x;
    int ln = t / 9;
    int c  = t - ln * 9;
    int i  = blockIdx.x * 32 + ln;
    if (i >= N_NODES) return;

    const uint4* hs = (const uint4*)g_h1h;      // N x 9 chunks
    int beg = __ldg(&g_rowptr[i]);
    int end = __ldg(&g_rowptr[i + 1]);

    float a[8] = {0, 0, 0, 0, 0, 0, 0, 0};
    acc_chunk(a, __ldg(&hs[(unsigned)i * 9 + c]));      // self loop

    int k = beg;
    for (; k + 3 < end; k += 4) {
        int s0 = __ldg(&g_esrc[k]);
        int s1 = __ldg(&g_esrc[k + 1]);
        int s2 = __ldg(&g_esrc[k + 2]);
        int s3 = __ldg(&g_esrc[k + 3]);
        uint4 q0 = __ldg(&hs[(unsigned)s0 * 9 + c]);
        uint4 q1 = __ldg(&hs[(unsigned)s1 * 9 + c]);
        uint4 q2 = __ldg(&hs[(unsigned)s2 * 9 + c]);
        uint4 q3 = __ldg(&hs[(unsigned)s3 * 9 + c]);
        acc_chunk(a, q0); acc_chunk(a, q1); acc_chunk(a, q2); acc_chunk(a, q3);
    }
    for (; k < end; k++) {
        int s = __ldg(&g_esrc[k]);
        acc_chunk(a, __ldg(&hs[(unsigned)s * 9 + c]));
    }

    float d = __ldg(&g_dinv[i]);
    float4 o0 = make_float4(d * a[0], d * a[1], d * a[2], d * a[3]);
    float4 o1 = make_float4(d * a[4], d * a[5], d * a[6], d * a[7]);
    g_agg1[(unsigned)i * 18 + c * 2]     = o0;
    g_agg1[(unsigned)i * 18 + c * 2 + 1] = o1;
}

// ---------------- GEMM2: hs2 = (relu(agg1 + b1) @ W2) * dinv -> fp16 --------
__global__ __launch_bounds__(256) void k_gemm2(const float* __restrict__ W2,
                                               const float* __restrict__ b1) {
    __shared__ float Ws[D_H1 * D_H2];  // 65x64 (16.6 KB)
    __shared__ float xs[128 * 33];     // stride 33
    const float* a1f = (const float*)g_agg1;
    int t = threadIdx.x;

    for (int idx = t; idx < D_H1 * D_H2; idx += 256) Ws[idx] = W2[idx];

    int g     = t & 3;
    int rp    = (t >> 2) * 2;
    int rbase = blockIdx.x * 128;

    float acc0[16], acc1[16];
#pragma unroll
    for (int j = 0; j < 16; j++) { acc0[j] = 0.0f; acc1[j] = 0.0f; }

    int k0 = 0;
    for (int kc = 0; kc < 2; kc++) {
        int len = kc ? 32 : 33;
        __syncthreads();
        for (int idx = t; idx < 128 * len; idx += 256) {
            int rr = idx / len, kk = idx % len;
            int r = rbase + rr, k = k0 + kk;
            xs[rr * 33 + kk] =
                (r < N_NODES) ? fmaxf(a1f[(unsigned)r * H1H + k] + b1[k], 0.0f) : 0.0f;
        }
        __syncthreads();
        for (int kk = 0; kk < len; kk++) {
            float xv0 = xs[rp * 33 + kk];
            float xv1 = xs[(rp + 1) * 33 + kk];
            const float* wr = &Ws[(k0 + kk) * D_H2 + g];
#pragma unroll
            for (int j = 0; j < 16; j++) {
                float w = wr[4 * j];
                acc0[j] += xv0 * w;
                acc1[j] += xv1 * w;
            }
        }
        k0 += len;
    }

    __half* hs = (__half*)g_h2h;
    int r0 = rbase + rp;
    if (r0 < N_NODES) {
        float d = g_dinv[r0];
#pragma unroll
        for (int j = 0; j < 16; j++)
            hs[r0 * D_H2 + g + 4 * j] = __float2half_rn(acc0[j] * d);
    }
    int r1 = r0 + 1;
    if (r1 < N_NODES) {
        float d = g_dinv[r1];
#pragma unroll
        for (int j = 0; j < 16; j++)
            hs[r1 * D_H2 + g + 4 * j] = __float2half_rn(acc1[j] * d);
    }
}

// ------- agg2 + output fused: out[i]=relu(sum_c relu(agg2_c+b2)*Wout + bout) -
// 8 chunk-threads per node, 32 nodes per 256-thread block.
__global__ __launch_bounds__(256) void k_agg2out(const float* __restrict__ b2,
                                                 const float* __restrict__ Wout,
                                                 const float* __restrict__ bout,
                                                 float* __restrict__ out) {
    int t  = threadIdx.x;
    int ln = t >> 3;
    int c  = t & 7;
    int i  = blockIdx.x * 32 + ln;
    if (i >= N_NODES) return;

    const uint4* hs = (const uint4*)g_h2h;      // N x 8 chunks
    int beg = __ldg(&g_rowptr[i]);
    int end = __ldg(&g_rowptr[i + 1]);

    float a[8] = {0, 0, 0, 0, 0, 0, 0, 0};
    acc_chunk(a, __ldg(&hs[(unsigned)i * 8 + c]));      // self loop

    int k = beg;
    for (; k + 3 < end; k += 4) {
        int s0 = __ldg(&g_esrc[k]);
        int s1 = __ldg(&g_esrc[k + 1]);
        int s2 = __ldg(&g_esrc[k + 2]);
        int s3 = __ldg(&g_esrc[k + 3]);
        uint4 q0 = __ldg(&hs[(unsigned)s0 * 8 + c]);
        uint4 q1 = __ldg(&hs[(unsigned)s1 * 8 + c]);
        uint4 q2 = __ldg(&hs[(unsigned)s2 * 8 + c]);
        uint4 q3 = __ldg(&hs[(unsigned)s3 * 8 + c]);
        acc_chunk(a, q0); acc_chunk(a, q1); acc_chunk(a, q2); acc_chunk(a, q3);
    }
    for (; k < end; k++) {
        int s = __ldg(&g_esrc[k]);
        acc_chunk(a, __ldg(&hs[(unsigned)s * 8 + c]));
    }

    float d = __ldg(&g_dinv[i]);
    float4 b2a = __ldg((const float4*)b2 + c * 2);
    float4 b2b = __ldg((const float4*)b2 + c * 2 + 1);
    float4 woa = __ldg((const float4*)Wout + c * 2);
    float4 wob = __ldg((const float4*)Wout + c * 2 + 1);

    float s = fmaxf(d * a[0] + b2a.x, 0.0f) * woa.x
            + fmaxf(d * a[1] + b2a.y, 0.0f) * woa.y
            + fmaxf(d * a[2] + b2a.z, 0.0f) * woa.z
            + fmaxf(d * a[3] + b2a.w, 0.0f) * woa.w
            + fmaxf(d * a[4] + b2b.x, 0.0f) * wob.x
            + fmaxf(d * a[5] + b2b.y, 0.0f) * wob.y
            + fmaxf(d * a[6] + b2b.z, 0.0f) * wob.z
            + fmaxf(d * a[7] + b2b.w, 0.0f) * wob.w;

    s += __shfl_xor_sync(0xffffffffu, s, 1);
    s += __shfl_xor_sync(0xffffffffu, s, 2);
    s += __shfl_xor_sync(0xffffffffu, s, 4);
    if (c == 0) out[i] = fmaxf(s + __ldg(bout), 0.0f);
}

// ---------------- launch ----------------------------------------------------
extern "C" void kernel_launch(void* const* d_in, const int* in_sizes, int n_in,
                              void* d_out, int out_size) {
    const float* x    = (const float*)d_in[0];
    const int*   ei   = (const int*)  d_in[1];
    const float* W1   = (const float*)d_in[2];
    const float* b1   = (const float*)d_in[3];
    const float* W2   = (const float*)d_in[4];
    const float* b2   = (const float*)d_in[5];
    const float* Wout = (const float*)d_in[6];
    const float* bout = (const float*)d_in[7];
    float* out = (float*)d_out;

    const int NB_N = (N_NODES + 255) / 256;
    const int NB_E = (N_EDGES + 255) / 256;
    const int NB_G = (N_NODES + 127) / 128;
    const int NB_A = (N_NODES + 31) / 32;    // 6250

    k_deg_zero <<<NB_N, 256>>>();
    k_deg_count<<<NB_E, 256>>>(ei);
    k_dinv     <<<NB_N, 256>>>();
    k_scan1    <<<SCAN_NB, SCAN_B>>>();
    k_scan2    <<<1, 256>>>();
    k_scan3    <<<SCAN_NB, SCAN_B>>>();
    k_scatter  <<<NB_E, 256>>>(ei);
    k_gemm1    <<<NB_G, 256>>>(x, W1);
    k_agg1     <<<NB_A, 288>>>();
    k_gemm2    <<<NB_G, 256>>>(W2, b1);
    k_agg2out  <<<NB_A, 256>>>(b2, Wout, bout, out);
}